// round 2
// baseline (speedup 1.0000x reference)
#include <cuda_runtime.h>

#define S_LEN 2048
#define B_SZ  512
#define HID   64
#define NGATE 256
#define ROWS  4
#define NCTA  (B_SZ / ROWS)   // 128
#define NTHR  256

// Ping-pong sequence buffers for inter-layer hidden states: (S, B, H) fp32.
__device__ float g_seq0[S_LEN * B_SZ * HID];
__device__ float g_seq1[S_LEN * B_SZ * HID];

__device__ __forceinline__ float sigm_f(float x) {
    // 1/(1+exp(-x)) via MUFU EX2 + RCP; few-ulp accuracy.
    float e = __expf(-x);
    return __fdividef(1.0f, 1.0f + e);
}
__device__ __forceinline__ float tanh_f(float x) {
    // tanh(|x|) = (1-e)/(1+e), e = exp(-2|x|); sign restored. No inf/NaN issues.
    float a = fabsf(x);
    float e = __expf(-2.0f * a);
    float t = __fdividef(1.0f - e, 1.0f + e);
    return copysignf(t, x);
}

// SRC: 0 -> g_seq0, 1 -> g_seq1, 2 -> external x (B, S, IN_DIM)
// DST: 0 -> g_seq0, 1 -> g_seq1, 2 -> no sequence output
template <int IN_DIM, int SRC, int DST, bool FINAL>
__global__ __launch_bounds__(NTHR, 1)
void lstm_layer_kernel(const float* __restrict__ x_ext,
                       const float* __restrict__ Wih,
                       const float* __restrict__ Whh,
                       const float* __restrict__ bih,
                       const float* __restrict__ bhh,
                       const float* __restrict__ fc_w,
                       const float* __restrict__ fc_b,
                       float* __restrict__ out_fc)
{
    const int tid = threadIdx.x;
    const int b0  = blockIdx.x * ROWS;

    const float* in_seq  = (SRC == 0) ? g_seq0 : (SRC == 1) ? g_seq1 : x_ext;
    float*       out_seq = (DST == 0) ? g_seq0 : (DST == 1) ? g_seq1 : nullptr;

    __shared__ __align__(16) float h_s[ROWS][HID];
    __shared__ __align__(16) float x_s[ROWS][IN_DIM];
    __shared__ float gates_s[ROWS][NGATE];

    // --- per-thread weights in registers: thread owns gate g = tid ---
    float whh[HID];
    float wih[IN_DIM];
    #pragma unroll
    for (int k = 0; k < HID; k++)    whh[k] = Whh[tid * HID + k];
    #pragma unroll
    for (int k = 0; k < IN_DIM; k++) wih[k] = Wih[tid * IN_DIM + k];
    const float bsum = bih[tid] + bhh[tid];

    // --- state init ---
    const int urow = tid >> 6, uj = tid & 63;
    h_s[urow][uj] = 0.0f;
    float c_reg = 0.0f;

    // --- input staging map: ROWS*IN_DIM elements, <= 1 per thread ---
    constexpr int XELEM = ROWS * IN_DIM;      // 256 (layers 1/2) or 16 (layer 0)
    const bool xi_act = (tid < XELEM);
    const int  xi_row = tid / IN_DIM;
    const int  xi_k   = tid - xi_row * IN_DIM;

    auto load_x = [&](int t) -> float {
        if (!xi_act) return 0.0f;
        if (SRC == 2) {
            // external x layout: (B, S, IN_DIM)
            return x_ext[(b0 + xi_row) * (S_LEN * IN_DIM) + t * IN_DIM + xi_k];
        } else {
            // sequence layout: (S, B, H)
            return in_seq[t * (B_SZ * HID) + (b0 + xi_row) * HID + xi_k];
        }
    };

    float x_pref = load_x(0);
    __syncthreads();

    for (int t = 0; t < S_LEN; t++) {
        // --- stage x_t; prefetch x_{t+1} (hidden under gate compute) ---
        if (xi_act) x_s[xi_row][xi_k] = x_pref;
        if (t + 1 < S_LEN) x_pref = load_x(t + 1);
        __syncthreads();   // x_s staged; h_s from previous update visible

        // --- gate compute: acc[r] = b + Whh[g,:]·h[r,:] + Wih[g,:]·x[r,:] ---
        float acc[ROWS];
        #pragma unroll
        for (int r = 0; r < ROWS; r++) acc[r] = bsum;

        #pragma unroll
        for (int k = 0; k < HID; k += 4) {
            #pragma unroll
            for (int r = 0; r < ROWS; r++) {
                float4 h4 = *reinterpret_cast<const float4*>(&h_s[r][k]);
                acc[r] = fmaf(whh[k + 0], h4.x, acc[r]);
                acc[r] = fmaf(whh[k + 1], h4.y, acc[r]);
                acc[r] = fmaf(whh[k + 2], h4.z, acc[r]);
                acc[r] = fmaf(whh[k + 3], h4.w, acc[r]);
                if (IN_DIM == HID) {
                    float4 x4 = *reinterpret_cast<const float4*>(&x_s[r][k]);
                    acc[r] = fmaf(wih[k + 0], x4.x, acc[r]);
                    acc[r] = fmaf(wih[k + 1], x4.y, acc[r]);
                    acc[r] = fmaf(wih[k + 2], x4.z, acc[r]);
                    acc[r] = fmaf(wih[k + 3], x4.w, acc[r]);
                }
            }
        }
        if (IN_DIM == 4) {
            #pragma unroll
            for (int r = 0; r < ROWS; r++) {
                float4 x4 = *reinterpret_cast<const float4*>(&x_s[r][0]);
                acc[r] = fmaf(wih[0], x4.x, acc[r]);
                acc[r] = fmaf(wih[1], x4.y, acc[r]);
                acc[r] = fmaf(wih[2], x4.z, acc[r]);
                acc[r] = fmaf(wih[3], x4.w, acc[r]);
            }
        }

        #pragma unroll
        for (int r = 0; r < ROWS; r++) gates_s[r][tid] = acc[r];
        __syncthreads();   // gates ready

        // --- state update: thread -> (urow, uj), c kept in register ---
        float gi = gates_s[urow][0 * HID + uj];
        float gf = gates_s[urow][1 * HID + uj];
        float gg = gates_s[urow][2 * HID + uj];
        float go = gates_s[urow][3 * HID + uj];

        float iv = sigm_f(gi);
        float fv = sigm_f(gf);
        float gv = tanh_f(gg);
        float ov = sigm_f(go);

        c_reg = fmaf(fv, c_reg, iv * gv);
        float hv = ov * tanh_f(c_reg);

        h_s[urow][uj] = hv;
        if (DST != 2) {
            out_seq[t * (B_SZ * HID) + (b0 + urow) * HID + uj] = hv;
        }
        __syncthreads();   // h_s consistent before next step (and before FC)
    }

    if (FINAL) {
        // final FC: out[b, o] = h[b, :]·fc_w[o, :] + fc_b[o]
        if (tid < ROWS * 2) {
            int r = tid >> 1, o = tid & 1;
            float s = fc_b[o];
            #pragma unroll
            for (int j = 0; j < HID; j++)
                s = fmaf(h_s[r][j], fc_w[o * HID + j], s);
            out_fc[(b0 + r) * 2 + o] = s;
        }
    }
}

extern "C" void kernel_launch(void* const* d_in, const int* in_sizes, int n_in,
                              void* d_out, int out_size)
{
    const float* x    = (const float*)d_in[0];
    const float* Wih0 = (const float*)d_in[1];
    const float* Whh0 = (const float*)d_in[2];
    const float* bih0 = (const float*)d_in[3];
    const float* bhh0 = (const float*)d_in[4];
    const float* Wih1 = (const float*)d_in[5];
    const float* Whh1 = (const float*)d_in[6];
    const float* bih1 = (const float*)d_in[7];
    const float* bhh1 = (const float*)d_in[8];
    const float* Wih2 = (const float*)d_in[9];
    const float* Whh2 = (const float*)d_in[10];
    const float* bih2 = (const float*)d_in[11];
    const float* bhh2 = (const float*)d_in[12];
    const float* fc_w = (const float*)d_in[13];
    const float* fc_b = (const float*)d_in[14];
    float* out = (float*)d_out;

    // layer 0: x (B,S,4) -> g_seq0
    lstm_layer_kernel<4, 2, 0, false><<<NCTA, NTHR>>>(
        x, Wih0, Whh0, bih0, bhh0, nullptr, nullptr, nullptr);
    // layer 1: g_seq0 -> g_seq1
    lstm_layer_kernel<HID, 0, 1, false><<<NCTA, NTHR>>>(
        nullptr, Wih1, Whh1, bih1, bhh1, nullptr, nullptr, nullptr);
    // layer 2: g_seq1 -> (no seq store) + fused FC -> out
    lstm_layer_kernel<HID, 1, 2, true><<<NCTA, NTHR>>>(
        nullptr, Wih2, Whh2, bih2, bhh2, fc_w, fc_b, out);
}